// round 4
// baseline (speedup 1.0000x reference)
#include <cuda_runtime.h>
#include <math.h>

#define Bz 16
#define Cc 512
#define Hh 28
#define Ww 28
#define Nn 784
#define NH 8
#define HD 64
#define Rr 32
#define HIDD 512
#define Mrows (Bz*Nn)   // 12544

// ---------------- scratch (device globals; no runtime allocation) ----------------
__device__ float g_avg[Bz*Cc];
__device__ float g_max[Bz*Cc];
__device__ float g_chs[Bz*Cc];
__device__ float g_y  [Bz*Cc*Nn];   // gated x, [B,C,N]
__device__ float g_q  [Mrows*Cc];   // [ (b*N+n), h*64+d ]
__device__ float g_k  [Mrows*Cc];
__device__ float g_v  [Mrows*Cc];
__device__ float g_att[Mrows*Cc];
__device__ float g_o  [Mrows*Cc];
__device__ float g_pool[Bz*Cc];

// ---------------- K1: channel pools (avg + max over HW) ----------------
__global__ void k_pool(const float* __restrict__ x) {
    int c = blockIdx.x, b = blockIdx.y;
    const float* p = x + ((long)(b*Cc + c))*Nn;
    float s = 0.f, m = -1e30f;
    for (int i = threadIdx.x; i < Nn; i += 256) { float v = p[i]; s += v; m = fmaxf(m, v); }
    __shared__ float ss[256], sm[256];
    ss[threadIdx.x] = s; sm[threadIdx.x] = m; __syncthreads();
    for (int o = 128; o > 0; o >>= 1) {
        if (threadIdx.x < o) { ss[threadIdx.x] += ss[threadIdx.x+o]; sm[threadIdx.x] = fmaxf(sm[threadIdx.x], sm[threadIdx.x+o]); }
        __syncthreads();
    }
    if (threadIdx.x == 0) { g_avg[b*Cc+c] = ss[0] / (float)Nn; g_max[b*Cc+c] = sm[0]; }
}

// ---------------- K2: channel-gate MLP + sigmoid ----------------
__global__ void k_changate(const float* __restrict__ w1, const float* __restrict__ b1,
                           const float* __restrict__ w2, const float* __restrict__ b2) {
    int b = blockIdx.x;
    __shared__ float sa[Cc], sx[Cc], ha[Rr], hm[Rr];
    for (int i = threadIdx.x; i < Cc; i += 256) { sa[i] = g_avg[b*Cc+i]; sx[i] = g_max[b*Cc+i]; }
    __syncthreads();
    if (threadIdx.x < Rr) {
        int r = threadIdx.x;
        float s1 = b1[r], s2 = b1[r];
        for (int i = 0; i < Cc; i++) { float w = w1[r*Cc+i]; s1 += w*sa[i]; s2 += w*sx[i]; }
        ha[r] = fmaxf(s1, 0.f); hm[r] = fmaxf(s2, 0.f);
    }
    __syncthreads();
    for (int c = threadIdx.x; c < Cc; c += 256) {
        float s = 2.f * b2[c];
        #pragma unroll
        for (int r = 0; r < Rr; r++) s += w2[c*Rr+r] * (ha[r] + hm[r]);
        g_chs[b*Cc+c] = 1.f / (1.f + expf(-s));
    }
}

// ---------------- K3: apply channel gate, spatial gate (7x7 conv + BN + sigmoid), apply ----------------
__global__ void k_spatial(const float* __restrict__ x, const float* __restrict__ sp_w,
                          const float* __restrict__ gam, const float* __restrict__ bet,
                          const float* __restrict__ mu,  const float* __restrict__ var) {
    int b = blockIdx.x;
    int p = threadIdx.x;            // 784 threads, one per pixel
    __shared__ float chs[Cc];
    __shared__ float cmax[Nn], cmean[Nn];
    __shared__ float wsm[98];
    if (p < Cc) chs[p] = g_chs[b*Cc+p];
    if (p >= Cc && p < Cc+98) wsm[p-Cc] = sp_w[p-Cc];
    __syncthreads();
    float mx = -1e30f, s = 0.f;
    for (int c = 0; c < Cc; c++) {
        float v = x[((long)(b*Cc+c))*Nn + p] * chs[c];
        g_y[((long)(b*Cc+c))*Nn + p] = v;
        mx = fmaxf(mx, v); s += v;
    }
    cmax[p] = mx; cmean[p] = s * (1.f/(float)Cc);
    __syncthreads();
    int py = p / Ww, px = p % Ww;
    float acc = 0.f;
    #pragma unroll
    for (int ky = 0; ky < 7; ky++) {
        int yy = py + ky - 3; if (yy < 0 || yy >= Hh) continue;
        #pragma unroll
        for (int kx = 0; kx < 7; kx++) {
            int xx = px + kx - 3; if (xx < 0 || xx >= Ww) continue;
            int q = yy*Ww + xx;
            acc += wsm[ky*7+kx] * cmax[q] + wsm[49+ky*7+kx] * cmean[q];
        }
    }
    float sv = (acc - mu[0]) * rsqrtf(var[0] + 1e-5f) * gam[0] + bet[0];
    float sg = 1.f / (1.f + expf(-sv));
    for (int c = 0; c < Cc; c++) {
        long idx = ((long)(b*Cc+c))*Nn + p;
        g_y[idx] = g_y[idx] * sg;
    }
}

// ---------------- K4: SGEMM  Out[m,n] = sum_k A[m,k]*W[n,k] + bias[n] ----------------
// MODE 0/1/2: A = g_y in [B,C,N] layout (transposed read) -> g_q/g_k/g_v
// MODE 3:     A = g_att row-major -> g_o
template<int MODE>
__global__ void k_gemm(const float* __restrict__ Wt, const float* __restrict__ bias) {
    const int BM = 64, BN = 64, BK = 32;
    __shared__ float As[BM][BK+1];
    __shared__ float Bs[BN][BK+1];
    int m0 = blockIdx.y * BM, n0 = blockIdx.x * BN;
    int tid = threadIdx.x;
    int tx = tid % 16, ty = tid / 16;
    float acc[4][4] = {};
    float* Out = (MODE==0) ? g_q : (MODE==1) ? g_k : (MODE==2) ? g_v : g_o;
    for (int k0 = 0; k0 < Cc; k0 += BK) {
        #pragma unroll
        for (int t = 0; t < 8; t++) {
            int li = tid + t*256;
            if (MODE < 3) {
                int mm = li % 64, kk = li / 64;
                int gm = m0 + mm;
                int bb = gm / Nn, nn = gm - bb*Nn;
                As[mm][kk] = g_y[((long)(bb*Cc + (k0+kk)))*Nn + nn];
            } else {
                int mm = li / 32, kk = li % 32;
                As[mm][kk] = g_att[(long)(m0+mm)*Cc + (k0+kk)];
            }
            int nn2 = li / 32, kk2 = li % 32;
            Bs[nn2][kk2] = Wt[(long)(n0+nn2)*Cc + (k0+kk2)];
        }
        __syncthreads();
        #pragma unroll
        for (int kk = 0; kk < BK; kk++) {
            float a[4], bv[4];
            #pragma unroll
            for (int i = 0; i < 4; i++) a[i]  = As[ty*4+i][kk];
            #pragma unroll
            for (int j = 0; j < 4; j++) bv[j] = Bs[tx*4+j][kk];
            #pragma unroll
            for (int i = 0; i < 4; i++)
                #pragma unroll
                for (int j = 0; j < 4; j++) acc[i][j] += a[i]*bv[j];
        }
        __syncthreads();
    }
    #pragma unroll
    for (int i = 0; i < 4; i++)
        #pragma unroll
        for (int j = 0; j < 4; j++)
            Out[(long)(m0+ty*4+i)*Cc + n0+tx*4+j] = acc[i][j] + bias[n0+tx*4+j];
}

// ---------------- K5: attention, one block per (b,h,n) row ----------------
__global__ void k_attn() {
    int n = blockIdx.x, h = blockIdx.y, b = blockIdx.z;
    int tid = threadIdx.x;  // 128
    __shared__ float q[HD];
    __shared__ float sc[Nn];
    __shared__ float red[128];
    const float* Qp = g_q + (long)(b*Nn+n)*Cc + h*HD;
    if (tid < HD) q[tid] = Qp[tid];
    __syncthreads();
    const float scale = 0.125f;  // 1/sqrt(64)
    for (int m = tid; m < Nn; m += 128) {
        const float* Kp = g_k + (long)(b*Nn+m)*Cc + h*HD;
        float s = 0.f;
        #pragma unroll
        for (int d = 0; d < HD; d += 4) {
            float4 kv = *(const float4*)(Kp + d);
            s += q[d]*kv.x + q[d+1]*kv.y + q[d+2]*kv.z + q[d+3]*kv.w;
        }
        sc[m] = s * scale;
    }
    __syncthreads();
    float mx = -1e30f;
    for (int m = tid; m < Nn; m += 128) mx = fmaxf(mx, sc[m]);
    red[tid] = mx; __syncthreads();
    for (int o = 64; o > 0; o >>= 1) { if (tid < o) red[tid] = fmaxf(red[tid], red[tid+o]); __syncthreads(); }
    mx = red[0]; __syncthreads();
    float se = 0.f;
    for (int m = tid; m < Nn; m += 128) { float e = __expf(sc[m] - mx); sc[m] = e; se += e; }
    red[tid] = se; __syncthreads();
    for (int o = 64; o > 0; o >>= 1) { if (tid < o) red[tid] += red[tid+o]; __syncthreads(); }
    float inv = 1.f / red[0];
    __syncthreads();
    int d = tid & 63, half = tid >> 6;   // split m-range across two groups of 64
    float acc = 0.f;
    int mbeg = half * 392, mend = mbeg + 392;
    for (int m = mbeg; m < mend; m++)
        acc += sc[m] * g_v[(long)(b*Nn+m)*Cc + h*HD + d];
    red[tid] = acc; __syncthreads();
    if (half == 0)
        g_att[(long)(b*Nn+n)*Cc + h*HD + d] = (red[d] + red[d+64]) * inv;
}

// ---------------- K6a: pooled sum of y over pixels (coalesced over p) ----------------
__global__ void k_pool_y() {
    int c = blockIdx.x, b = blockIdx.y;
    const float* p = g_y + (long)(b*Cc+c)*Nn;
    float s = 0.f;
    for (int i = threadIdx.x; i < Nn; i += 256) s += p[i];
    __shared__ float ss[256];
    ss[threadIdx.x] = s; __syncthreads();
    for (int o = 128; o > 0; o >>= 1) { if (threadIdx.x < o) ss[threadIdx.x] += ss[threadIdx.x+o]; __syncthreads(); }
    if (threadIdx.x == 0) g_pool[b*Cc+c] = ss[0];
}

// ---------------- K6b: add pooled sum of O (coalesced over c), deterministic ----------------
__global__ void k_pool_o() {
    int b = blockIdx.x;
    int c = threadIdx.x;   // 512 threads
    float s = 0.f;
    for (int p = 0; p < Nn; p++) s += g_o[(long)(b*Nn+p)*Cc + c];
    g_pool[b*Cc+c] += s;
}

// ---------------- K7: classifier (LN -> fc1 relu -> fc2) ----------------
__global__ void k_head(const float* __restrict__ lng, const float* __restrict__ lnb,
                       const float* __restrict__ f1w, const float* __restrict__ f1b,
                       const float* __restrict__ f2w, const float* __restrict__ f2b,
                       float* __restrict__ out) {
    int b = blockIdx.x, t = threadIdx.x;   // 512 threads
    __shared__ float pv[512], ln[512], hsm[512], red[512];
    pv[t] = g_pool[b*Cc+t] * (1.f/(float)Nn);
    __syncthreads();
    red[t] = pv[t]; __syncthreads();
    for (int o = 256; o > 0; o >>= 1) { if (t < o) red[t] += red[t+o]; __syncthreads(); }
    float mu = red[0] * (1.f/512.f); __syncthreads();
    float dv = pv[t] - mu;
    red[t] = dv*dv; __syncthreads();
    for (int o = 256; o > 0; o >>= 1) { if (t < o) red[t] += red[t+o]; __syncthreads(); }
    float var = red[0] * (1.f/512.f);
    float rs = rsqrtf(var + 1e-5f);
    ln[t] = dv * rs * lng[t] + lnb[t];
    __syncthreads();
    float s = f1b[t];
    for (int i = 0; i < 512; i++) s += f1w[t*512+i] * ln[i];
    hsm[t] = fmaxf(s, 0.f);
    __syncthreads();
    red[t] = f2w[t] * hsm[t]; __syncthreads();
    for (int o = 256; o > 0; o >>= 1) { if (t < o) red[t] += red[t+o]; __syncthreads(); }
    if (t == 0) out[b] = red[0] + f2b[0];
}

// ---------------- launch ----------------
extern "C" void kernel_launch(void* const* d_in, const int* in_sizes, int n_in,
                              void* d_out, int out_size) {
    const float* x       = (const float*)d_in[0];
    const float* mlp_w1  = (const float*)d_in[1];
    const float* mlp_b1  = (const float*)d_in[2];
    const float* mlp_w2  = (const float*)d_in[3];
    const float* mlp_b2  = (const float*)d_in[4];
    const float* sp_w    = (const float*)d_in[5];
    const float* sp_gam  = (const float*)d_in[6];
    const float* sp_bet  = (const float*)d_in[7];
    const float* sp_mean = (const float*)d_in[8];
    const float* sp_var  = (const float*)d_in[9];
    const float* wq      = (const float*)d_in[10];
    const float* bq      = (const float*)d_in[11];
    const float* wk      = (const float*)d_in[12];
    const float* bk      = (const float*)d_in[13];
    const float* wv      = (const float*)d_in[14];
    const float* bv      = (const float*)d_in[15];
    const float* wo      = (const float*)d_in[16];
    const float* bo      = (const float*)d_in[17];
    const float* ln_g    = (const float*)d_in[18];
    const float* ln_b    = (const float*)d_in[19];
    const float* fc1_w   = (const float*)d_in[20];
    const float* fc1_b   = (const float*)d_in[21];
    const float* fc2_w   = (const float*)d_in[22];
    const float* fc2_b   = (const float*)d_in[23];
    float* out = (float*)d_out;

    k_pool    <<<dim3(Cc, Bz), 256>>>(x);
    k_changate<<<Bz, 256>>>(mlp_w1, mlp_b1, mlp_w2, mlp_b2);
    k_spatial <<<Bz, Nn>>>(x, sp_w, sp_gam, sp_bet, sp_mean, sp_var);

    dim3 gg(Cc/64, Mrows/64);   // (8, 196)
    k_gemm<0><<<gg, 256>>>(wq, bq);
    k_gemm<1><<<gg, 256>>>(wk, bk);
    k_gemm<2><<<gg, 256>>>(wv, bv);

    k_attn<<<dim3(Nn, NH, Bz), 128>>>();

    k_gemm<3><<<gg, 256>>>(wo, bo);

    k_pool_y<<<dim3(Cc, Bz), 256>>>();
    k_pool_o<<<Bz, 512>>>();
    k_head  <<<Bz, 512>>>(ln_g, ln_b, fc1_w, fc1_b, fc2_w, fc2_b, out);
}

// round 6
// speedup vs baseline: 2.5699x; 2.5699x over previous
#include <cuda_runtime.h>
#include <math.h>

#define Bz 16
#define Cc 512
#define Hh 28
#define Ww 28
#define Nn 784
#define NH 8
#define HD 64
#define Rr 32
#define Mrows (Bz*Nn)   // 12544

// ---------------- scratch ----------------
__device__ float g_avg[Bz*Cc];
__device__ float g_max[Bz*Cc];
__device__ float g_chs[Bz*Cc];
__device__ float g_cmax[Bz*Nn];
__device__ float g_cmean[Bz*Nn];
__device__ float g_sg[Bz*Nn];       // spatial sigmoid map
__device__ float g_y  [Bz*Cc*Nn];   // channel-gated x, [B,C,N] (NOT yet spatially gated)
__device__ float g_q  [Mrows*Cc];
__device__ float g_k  [Mrows*Cc];
__device__ float g_v  [Mrows*Cc];
__device__ float g_att[Mrows*Cc];
__device__ float g_o  [Mrows*Cc];
__device__ float g_pool[Bz*Cc];
__device__ float g_part[Bz*8*Cc];

// ---------------- K1: channel pools (avg + max over HW) ----------------
__global__ void k_pool(const float* __restrict__ x) {
    int c = blockIdx.x, b = blockIdx.y;
    const float* p = x + ((long)(b*Cc + c))*Nn;
    float s = 0.f, m = -1e30f;
    for (int i = threadIdx.x; i < Nn; i += 256) { float v = p[i]; s += v; m = fmaxf(m, v); }
    __shared__ float ss[256], sm[256];
    ss[threadIdx.x] = s; sm[threadIdx.x] = m; __syncthreads();
    for (int o = 128; o > 0; o >>= 1) {
        if (threadIdx.x < o) { ss[threadIdx.x] += ss[threadIdx.x+o]; sm[threadIdx.x] = fmaxf(sm[threadIdx.x], sm[threadIdx.x+o]); }
        __syncthreads();
    }
    if (threadIdx.x == 0) { g_avg[b*Cc+c] = ss[0] / (float)Nn; g_max[b*Cc+c] = sm[0]; }
}

// ---------------- K2: channel-gate MLP + sigmoid ----------------
__global__ void k_changate(const float* __restrict__ w1, const float* __restrict__ b1,
                           const float* __restrict__ w2, const float* __restrict__ b2) {
    int b = blockIdx.x;
    __shared__ float sa[Cc], sx[Cc], ha[Rr], hm[Rr];
    for (int i = threadIdx.x; i < Cc; i += 256) { sa[i] = g_avg[b*Cc+i]; sx[i] = g_max[b*Cc+i]; }
    __syncthreads();
    if (threadIdx.x < Rr) {
        int r = threadIdx.x;
        float s1 = b1[r], s2 = b1[r];
        for (int i = 0; i < Cc; i++) { float w = w1[r*Cc+i]; s1 += w*sa[i]; s2 += w*sx[i]; }
        ha[r] = fmaxf(s1, 0.f); hm[r] = fmaxf(s2, 0.f);
    }
    __syncthreads();
    for (int c = threadIdx.x; c < Cc; c += 256) {
        float s = 2.f * b2[c];
        #pragma unroll
        for (int r = 0; r < Rr; r++) s += w2[c*Rr+r] * (ha[r] + hm[r]);
        g_chs[b*Cc+c] = 1.f / (1.f + expf(-s));
    }
}

// ---------------- K3a: apply channel gate, per-pixel channel max/mean ----------------
__global__ void k_gate1(const float* __restrict__ x) {
    int b = blockIdx.x;
    int p = blockIdx.y*196 + threadIdx.x;   // block 196 threads
    __shared__ float chs[Cc];
    for (int i = threadIdx.x; i < Cc; i += 196) chs[i] = g_chs[b*Cc+i];
    __syncthreads();
    float mxv = -1e30f, sv = 0.f;
    for (int c = 0; c < Cc; c++) {
        long idx = ((long)(b*Cc+c))*Nn + p;
        float v = x[idx] * chs[c];
        g_y[idx] = v;
        mxv = fmaxf(mxv, v); sv += v;
    }
    g_cmax[b*Nn+p] = mxv; g_cmean[b*Nn+p] = sv * (1.f/(float)Cc);
}

// ---------------- K3b: 7x7 conv + BN + sigmoid -> g_sg ----------------
__global__ void k_gate2(const float* __restrict__ sp_w,
                        const float* __restrict__ gam, const float* __restrict__ bet,
                        const float* __restrict__ mu,  const float* __restrict__ var) {
    int b = blockIdx.x, p = threadIdx.x;   // 784 threads
    __shared__ float cmax[Nn], cmean[Nn], wsm[98];
    cmax[p] = g_cmax[b*Nn+p]; cmean[p] = g_cmean[b*Nn+p];
    if (p < 98) wsm[p] = sp_w[p];
    __syncthreads();
    int py = p / Ww, px = p % Ww;
    float acc = 0.f;
    #pragma unroll
    for (int ky = 0; ky < 7; ky++) {
        int yy = py + ky - 3; if (yy < 0 || yy >= Hh) continue;
        #pragma unroll
        for (int kx = 0; kx < 7; kx++) {
            int xx = px + kx - 3; if (xx < 0 || xx >= Ww) continue;
            int q = yy*Ww + xx;
            acc += wsm[ky*7+kx] * cmax[q] + wsm[49+ky*7+kx] * cmean[q];
        }
    }
    float sv = (acc - mu[0]) * rsqrtf(var[0] + 1e-5f) * gam[0] + bet[0];
    g_sg[b*Nn+p] = 1.f / (1.f + expf(-sv));
}

// ---------------- K4: SGEMM 128x128x16, 8x8/thread ----------------
// MODE 0: A = g_y*g_sg (transposed read), z selects Q/K/V.  MODE 3: A = g_att row-major -> g_o
template<int MODE>
__global__ __launch_bounds__(256) void k_gemm2(const float* __restrict__ W0, const float* __restrict__ W1,
                        const float* __restrict__ W2, const float* __restrict__ bb0,
                        const float* __restrict__ bb1, const float* __restrict__ bb2) {
    __shared__ float As[16][132];
    __shared__ float Bs[16][132];
    int m0 = blockIdx.y*128, n0 = blockIdx.x*128;
    const float* W; const float* bias; float* Out;
    if (MODE == 0) {
        int z = blockIdx.z;
        W    = (z==0) ? W0 : (z==1) ? W1 : W2;
        bias = (z==0) ? bb0 : (z==1) ? bb1 : bb2;
        Out  = (z==0) ? g_q : (z==1) ? g_k : g_v;
    } else { W = W0; bias = bb0; Out = g_o; }
    int tid = threadIdx.x;
    int tx = tid & 15, ty = tid >> 4;
    float acc[8][8] = {};
    for (int k0 = 0; k0 < Cc; k0 += 16) {
        if (MODE == 0) {
            #pragma unroll
            for (int t = 0; t < 8; t++) {
                int idx = tid + t*256;
                int mm = idx & 127, kk = idx >> 7;
                int gm = m0 + mm;
                int bb = gm / Nn, nn = gm - bb*Nn;
                As[kk][mm] = g_y[((long)(bb*Cc + k0+kk))*Nn + nn] * g_sg[gm];
            }
        } else {
            #pragma unroll
            for (int t = 0; t < 8; t++) {
                int idx = tid + t*256;
                int kk = idx & 15, mm = idx >> 4;
                As[kk][mm] = g_att[(long)(m0+mm)*Cc + k0+kk];
            }
        }
        #pragma unroll
        for (int t = 0; t < 8; t++) {
            int idx = tid + t*256;
            int kk = idx & 15, nn = idx >> 4;
            Bs[kk][nn] = W[(long)(n0+nn)*Cc + k0+kk];
        }
        __syncthreads();
        #pragma unroll
        for (int kk = 0; kk < 16; kk++) {
            float4 a0 = *(float4*)&As[kk][ty*4];
            float4 a1 = *(float4*)&As[kk][64+ty*4];
            float4 b0 = *(float4*)&Bs[kk][tx*4];
            float4 b1 = *(float4*)&Bs[kk][64+tx*4];
            float a[8] = {a0.x,a0.y,a0.z,a0.w,a1.x,a1.y,a1.z,a1.w};
            float bv[8] = {b0.x,b0.y,b0.z,b0.w,b1.x,b1.y,b1.z,b1.w};
            #pragma unroll
            for (int i = 0; i < 8; i++)
                #pragma unroll
                for (int j = 0; j < 8; j++) acc[i][j] += a[i]*bv[j];
        }
        __syncthreads();
    }
    float bj[8];
    #pragma unroll
    for (int j = 0; j < 4; j++) { bj[j] = bias[n0+tx*4+j]; bj[4+j] = bias[n0+64+tx*4+j]; }
    #pragma unroll
    for (int ih = 0; ih < 2; ih++) {
        #pragma unroll
        for (int i = 0; i < 4; i++) {
            int row = m0 + ih*64 + ty*4 + i;
            int ai = ih*4 + i;
            float* op = Out + (long)row*Cc + n0;
            float4 o0 = {acc[ai][0]+bj[0], acc[ai][1]+bj[1], acc[ai][2]+bj[2], acc[ai][3]+bj[3]};
            float4 o1 = {acc[ai][4]+bj[4], acc[ai][5]+bj[5], acc[ai][6]+bj[6], acc[ai][7]+bj[7]};
            *(float4*)&op[tx*4]    = o0;
            *(float4*)&op[64+tx*4] = o1;
        }
    }
}

// ---------------- K5: tiled attention, 16 query rows / block ----------------
#define MT 16
#define KT 128
__global__ __launch_bounds__(256) void k_attn2() {
    extern __shared__ float smn[];
    float (*sc)[MT] = (float (*)[MT])smn;                      // [784][16]
    float (*Qs)[65] = (float (*)[65])(smn + Nn*MT);            // [16][65]
    float (*Ks)[65] = (float (*)[65])(smn + Nn*MT + MT*65);    // [128][65]
    __shared__ float mxs[MT], inv[MT], red2[16][MT];
    int n0 = blockIdx.x*MT, h = blockIdx.y, b = blockIdx.z;
    int tid = threadIdx.x;
    for (int idx = tid; idx < MT*HD; idx += 256) {
        int r = idx >> 6, d = idx & 63;
        Qs[r][d] = g_q[((long)(b*Nn + n0 + r))*Cc + h*HD + d];
    }
    int tx = tid & 63, ty = tid >> 6;
    for (int kt = 0; kt < Nn; kt += KT) {
        __syncthreads();
        for (int idx = tid; idx < KT*HD; idx += 256) {
            int r = idx >> 6, d = idx & 63;
            int m = kt + r; if (m > Nn-1) m = Nn-1;
            Ks[r][d] = g_k[((long)(b*Nn + m))*Cc + h*HD + d];
        }
        __syncthreads();
        float acc[4][2] = {};
        #pragma unroll 8
        for (int d = 0; d < HD; d++) {
            float k0v = Ks[tx][d], k1v = Ks[tx+64][d];
            #pragma unroll
            for (int i = 0; i < 4; i++) {
                float q = Qs[ty*4+i][d];
                acc[i][0] += q*k0v; acc[i][1] += q*k1v;
            }
        }
        const float scale = 0.125f;
        int c0 = kt + tx, c1 = kt + tx + 64;
        if (c0 < Nn) {
            float4 v = {acc[0][0]*scale, acc[1][0]*scale, acc[2][0]*scale, acc[3][0]*scale};
            *(float4*)&sc[c0][ty*4] = v;
        }
        if (c1 < Nn) {
            float4 v = {acc[0][1]*scale, acc[1][1]*scale, acc[2][1]*scale, acc[3][1]*scale};
            *(float4*)&sc[c1][ty*4] = v;
        }
    }
    __syncthreads();
    // softmax over m for each of the 16 rows
    int r = tid & 15, grp = tid >> 4;
    float m_ = -1e30f;
    for (int m = grp; m < Nn; m += 16) m_ = fmaxf(m_, sc[m][r]);
    red2[grp][r] = m_; __syncthreads();
    if (tid < MT) { float v = -1e30f; for (int g = 0; g < 16; g++) v = fmaxf(v, red2[g][tid]); mxs[tid] = v; }
    __syncthreads();
    float s_ = 0.f; float mxr = mxs[r];
    for (int m = grp; m < Nn; m += 16) { float e = __expf(sc[m][r] - mxr); sc[m][r] = e; s_ += e; }
    red2[grp][r] = s_; __syncthreads();
    if (tid < MT) { float v = 0.f; for (int g = 0; g < 16; g++) v += red2[g][tid]; inv[tid] = 1.f/v; }
    // AV
    int dd = tid >> 2, tg = tid & 3;
    float oa[4] = {};
    for (int vt = 0; vt < Nn; vt += KT) {
        __syncthreads();
        for (int idx = tid; idx < KT*HD; idx += 256) {
            int rr = idx >> 6, d2 = idx & 63;
            int m = vt + rr; if (m > Nn-1) m = Nn-1;
            Ks[rr][d2] = g_v[((long)(b*Nn + m))*Cc + h*HD + d2];
        }
        __syncthreads();
        int mmax = (Nn - vt < KT) ? (Nn - vt) : KT;
        for (int m2 = 0; m2 < mmax; m2++) {
            float v = Ks[m2][dd];
            float4 p = *(float4*)&sc[vt+m2][tg*4];
            oa[0] += p.x*v; oa[1] += p.y*v; oa[2] += p.z*v; oa[3] += p.w*v;
        }
    }
    #pragma unroll
    for (int i = 0; i < 4; i++) {
        int row = tg*4 + i;
        g_att[((long)(b*Nn + n0 + row))*Cc + h*HD + dd] = oa[i]*inv[row];
    }
}

// ---------------- K6a: pooled sum of y*sg over pixels ----------------
__global__ void k_pool_y2() {
    int c = blockIdx.x, b = blockIdx.y;
    const float* p = g_y + (long)(b*Cc+c)*Nn;
    const float* sg = g_sg + b*Nn;
    float s = 0.f;
    for (int i = threadIdx.x; i < Nn; i += 256) s += p[i]*sg[i];
    __shared__ float ss[256];
    ss[threadIdx.x] = s; __syncthreads();
    for (int o = 128; o > 0; o >>= 1) { if (threadIdx.x < o) ss[threadIdx.x] += ss[threadIdx.x+o]; __syncthreads(); }
    if (threadIdx.x == 0) g_pool[b*Cc+c] = ss[0];
}

// ---------------- K6b: partial pooled sums of O ----------------
__global__ void k_pool_o2() {
    int b = blockIdx.x, chunk = blockIdx.y;
    int p0 = chunk*98;
    int c = threadIdx.x;     // 256 threads, 2 channels each
    float s0 = 0.f, s1 = 0.f;
    for (int p = p0; p < p0+98; p++) {
        const float* row = g_o + (long)(b*Nn+p)*Cc;
        s0 += row[c]; s1 += row[c+256];
    }
    g_part[(long)(b*8+chunk)*Cc + c]       = s0;
    g_part[(long)(b*8+chunk)*Cc + c + 256] = s1;
}

// ---------------- K7: classifier ----------------
__global__ void k_head(const float* __restrict__ lng, const float* __restrict__ lnb,
                       const float* __restrict__ f1w, const float* __restrict__ f1b,
                       const float* __restrict__ f2w, const float* __restrict__ f2b,
                       float* __restrict__ out) {
    int b = blockIdx.x, t = threadIdx.x;   // 512 threads
    __shared__ float pv[512], ln[512], hsm[512], red[512];
    float acc = g_pool[b*Cc+t];
    #pragma unroll
    for (int j = 0; j < 8; j++) acc += g_part[(long)(b*8+j)*Cc + t];
    pv[t] = acc * (1.f/(float)Nn);
    __syncthreads();
    red[t] = pv[t]; __syncthreads();
    for (int o = 256; o > 0; o >>= 1) { if (t < o) red[t] += red[t+o]; __syncthreads(); }
    float mu = red[0] * (1.f/512.f); __syncthreads();
    float dv = pv[t] - mu;
    red[t] = dv*dv; __syncthreads();
    for (int o = 256; o > 0; o >>= 1) { if (t < o) red[t] += red[t+o]; __syncthreads(); }
    float var = red[0] * (1.f/512.f);
    float rs = rsqrtf(var + 1e-5f);
    ln[t] = dv * rs * lng[t] + lnb[t];
    __syncthreads();
    float s = f1b[t];
    for (int i = 0; i < 512; i++) s += f1w[t*512+i] * ln[i];
    hsm[t] = fmaxf(s, 0.f);
    __syncthreads();
    red[t] = f2w[t] * hsm[t]; __syncthreads();
    for (int o = 256; o > 0; o >>= 1) { if (t < o) red[t] += red[t+o]; __syncthreads(); }
    if (t == 0) out[b] = red[0] + f2b[0];
}

// ---------------- launch ----------------
extern "C" void kernel_launch(void* const* d_in, const int* in_sizes, int n_in,
                              void* d_out, int out_size) {
    const float* x       = (const float*)d_in[0];
    const float* mlp_w1  = (const float*)d_in[1];
    const float* mlp_b1  = (const float*)d_in[2];
    const float* mlp_w2  = (const float*)d_in[3];
    const float* mlp_b2  = (const float*)d_in[4];
    const float* sp_w    = (const float*)d_in[5];
    const float* sp_gam  = (const float*)d_in[6];
    const float* sp_bet  = (const float*)d_in[7];
    const float* sp_mean = (const float*)d_in[8];
    const float* sp_var  = (const float*)d_in[9];
    const float* wq      = (const float*)d_in[10];
    const float* bq      = (const float*)d_in[11];
    const float* wk      = (const float*)d_in[12];
    const float* bk      = (const float*)d_in[13];
    const float* wv      = (const float*)d_in[14];
    const float* bv      = (const float*)d_in[15];
    const float* wo      = (const float*)d_in[16];
    const float* bo      = (const float*)d_in[17];
    const float* ln_g    = (const float*)d_in[18];
    const float* ln_b    = (const float*)d_in[19];
    const float* fc1_w   = (const float*)d_in[20];
    const float* fc1_b   = (const float*)d_in[21];
    const float* fc2_w   = (const float*)d_in[22];
    const float* fc2_b   = (const float*)d_in[23];
    float* out = (float*)d_out;

    static int attn_smem_set = 0;
    int attn_smem = (Nn*MT + MT*65 + KT*65) * 4;   // 87,616 B
    if (!attn_smem_set) {
        cudaFuncSetAttribute(k_attn2, cudaFuncAttributeMaxDynamicSharedMemorySize, attn_smem);
        attn_smem_set = 1;
    }

    k_pool    <<<dim3(Cc, Bz), 256>>>(x);
    k_changate<<<Bz, 256>>>(mlp_w1, mlp_b1, mlp_w2, mlp_b2);
    k_gate1   <<<dim3(Bz, 4), 196>>>(x);
    k_gate2   <<<Bz, Nn>>>(sp_w, sp_gam, sp_bet, sp_mean, sp_var);

    k_gemm2<0><<<dim3(4, 98, 3), 256>>>(wq, wk, wv, bq, bk, bv);

    k_attn2<<<dim3(Nn/MT, NH, Bz), 256, attn_smem>>>();

    k_gemm2<3><<<dim3(4, 98, 1), 256>>>(wo, 0, 0, bo, 0, 0);

    k_pool_y2<<<dim3(Cc, Bz), 256>>>();
    k_pool_o2<<<dim3(Bz, 8), 256>>>();
    k_head  <<<Bz, 512>>>(ln_g, ln_b, fc1_w, fc1_b, fc2_w, fc2_b, out);
}

// round 8
// speedup vs baseline: 4.3392x; 1.6885x over previous
#include <cuda_runtime.h>
#include <math.h>

#define Bz 16
#define Cc 512
#define Hh 28
#define Ww 28
#define Nn 784
#define NH 8
#define HD 64
#define Rr 32
#define Mrows (Bz*Nn)   // 12544

// ---------------- scratch ----------------
__device__ float g_avg[Bz*Cc];
__device__ float g_max[Bz*Cc];
__device__ float g_chs[Bz*Cc];
__device__ float g_pmax[Bz*8*Nn];
__device__ float g_psum[Bz*8*Nn];
__device__ float g_sg[Bz*Nn];       // spatial sigmoid map
__device__ float g_q  [Mrows*Cc];
__device__ float g_k  [Mrows*Cc];
__device__ float g_v  [Mrows*Cc];
__device__ float g_att[Mrows*Cc];
__device__ float g_o  [Mrows*Cc];
__device__ float g_pool[Bz*Cc];
__device__ float g_part[Bz*16*Cc];

// ---------------- K1: channel pools (avg + max over HW) ----------------
__global__ void k_pool(const float* __restrict__ x) {
    int c = blockIdx.x, b = blockIdx.y;
    const float4* p = (const float4*)(x + ((long)(b*Cc + c))*Nn);
    float s = 0.f, m = -1e30f;
    for (int i = threadIdx.x; i < Nn/4; i += 256) {
        float4 v = p[i];
        s += v.x+v.y+v.z+v.w;
        m = fmaxf(m, fmaxf(fmaxf(v.x,v.y), fmaxf(v.z,v.w)));
    }
    __shared__ float ss[256], sm[256];
    ss[threadIdx.x] = s; sm[threadIdx.x] = m; __syncthreads();
    for (int o = 128; o > 0; o >>= 1) {
        if (threadIdx.x < o) { ss[threadIdx.x] += ss[threadIdx.x+o]; sm[threadIdx.x] = fmaxf(sm[threadIdx.x], sm[threadIdx.x+o]); }
        __syncthreads();
    }
    if (threadIdx.x == 0) { g_avg[b*Cc+c] = ss[0] / (float)Nn; g_max[b*Cc+c] = sm[0]; }
}

// ---------------- K2: channel-gate MLP + sigmoid ----------------
__global__ void k_changate(const float* __restrict__ w1, const float* __restrict__ b1,
                           const float* __restrict__ w2, const float* __restrict__ b2) {
    int b = blockIdx.x;
    __shared__ float sa[Cc], sx[Cc], ha[Rr], hm[Rr];
    for (int i = threadIdx.x; i < Cc; i += 256) { sa[i] = g_avg[b*Cc+i]; sx[i] = g_max[b*Cc+i]; }
    __syncthreads();
    if (threadIdx.x < Rr) {
        int r = threadIdx.x;
        float s1 = b1[r], s2 = b1[r];
        for (int i = 0; i < Cc; i++) { float w = w1[r*Cc+i]; s1 += w*sa[i]; s2 += w*sx[i]; }
        ha[r] = fmaxf(s1, 0.f); hm[r] = fmaxf(s2, 0.f);
    }
    __syncthreads();
    for (int c = threadIdx.x; c < Cc; c += 256) {
        float s = 2.f * b2[c];
        #pragma unroll
        for (int r = 0; r < Rr; r++) s += w2[c*Rr+r] * (ha[r] + hm[r]);
        g_chs[b*Cc+c] = 1.f / (1.f + expf(-s));
    }
}

// ---------------- K3a: per-pixel channel max/mean over 64-channel chunk ----------------
__global__ void k_gate1(const float* __restrict__ x) {
    int b = blockIdx.x, pc = blockIdx.y, cch = blockIdx.z;   // grid (Bz,4,8), 196 thr
    int p = pc*196 + threadIdx.x;
    __shared__ float chs[64];
    if (threadIdx.x < 64) chs[threadIdx.x] = g_chs[b*Cc + cch*64 + threadIdx.x];
    __syncthreads();
    float mx = -1e30f, s = 0.f;
    #pragma unroll 8
    for (int c0 = 0; c0 < 64; c0++) {
        int c = cch*64 + c0;
        float v = x[((long)(b*Cc+c))*Nn + p] * chs[c0];
        mx = fmaxf(mx, v); s += v;
    }
    g_pmax[(b*8+cch)*Nn + p] = mx;
    g_psum[(b*8+cch)*Nn + p] = s;
}

// ---------------- K3b: reduce chunks, 7x7 conv + BN + sigmoid -> g_sg ----------------
__global__ void k_gate2(const float* __restrict__ sp_w,
                        const float* __restrict__ gam, const float* __restrict__ bet,
                        const float* __restrict__ mu,  const float* __restrict__ var) {
    int b = blockIdx.x, p = threadIdx.x;   // 784 threads
    __shared__ float cmax[Nn], cmean[Nn], wsm[98];
    float mx = -1e30f, s = 0.f;
    #pragma unroll
    for (int ch = 0; ch < 8; ch++) {
        mx = fmaxf(mx, g_pmax[(b*8+ch)*Nn + p]);
        s += g_psum[(b*8+ch)*Nn + p];
    }
    cmax[p] = mx; cmean[p] = s * (1.f/(float)Cc);
    if (p < 98) wsm[p] = sp_w[p];
    __syncthreads();
    int py = p / Ww, px = p % Ww;
    float acc = 0.f;
    #pragma unroll
    for (int ky = 0; ky < 7; ky++) {
        int yy = py + ky - 3; if (yy < 0 || yy >= Hh) continue;
        #pragma unroll
        for (int kx = 0; kx < 7; kx++) {
            int xx = px + kx - 3; if (xx < 0 || xx >= Ww) continue;
            int q = yy*Ww + xx;
            acc += wsm[ky*7+kx] * cmax[q] + wsm[49+ky*7+kx] * cmean[q];
        }
    }
    float sv = (acc - mu[0]) * rsqrtf(var[0] + 1e-5f) * gam[0] + bet[0];
    g_sg[b*Nn+p] = 1.f / (1.f + expf(-sv));
}

// ---------------- K4: SGEMM 128x128x16, 8x8/thread ----------------
template<int MODE>
__global__ __launch_bounds__(256) void k_gemm2(const float* __restrict__ X,
                        const float* __restrict__ W0, const float* __restrict__ W1,
                        const float* __restrict__ W2, const float* __restrict__ bb0,
                        const float* __restrict__ bb1, const float* __restrict__ bb2) {
    __shared__ float As[16][132];
    __shared__ float Bs[16][132];
    int m0 = blockIdx.y*128, n0 = blockIdx.x*128;
    const float* W; const float* bias; float* Out;
    if (MODE == 0) {
        int z = blockIdx.z;
        W    = (z==0) ? W0 : (z==1) ? W1 : W2;
        bias = (z==0) ? bb0 : (z==1) ? bb1 : bb2;
        Out  = (z==0) ? g_q : (z==1) ? g_k : g_v;
    } else { W = W0; bias = bb0; Out = g_o; }
    int tid = threadIdx.x;
    int tx = tid & 15, ty = tid >> 4;
    float acc[8][8] = {};
    for (int k0 = 0; k0 < Cc; k0 += 16) {
        if (MODE == 0) {
            #pragma unroll
            for (int t = 0; t < 8; t++) {
                int idx = tid + t*256;
                int mm = idx & 127, kk = idx >> 7;
                int gm = m0 + mm;
                int bb = gm / Nn, nn = gm - bb*Nn;
                As[kk][mm] = X[((long)(bb*Cc + k0+kk))*Nn + nn]
                           * g_chs[bb*Cc + k0+kk] * g_sg[gm];
            }
        } else {
            #pragma unroll
            for (int t = 0; t < 8; t++) {
                int idx = tid + t*256;
                int kk = idx & 15, mm = idx >> 4;
                As[kk][mm] = g_att[(long)(m0+mm)*Cc + k0+kk];
            }
        }
        #pragma unroll
        for (int t = 0; t < 8; t++) {
            int idx = tid + t*256;
            int kk = idx & 15, nn = idx >> 4;
            Bs[kk][nn] = W[(long)(n0+nn)*Cc + k0+kk];
        }
        __syncthreads();
        #pragma unroll
        for (int kk = 0; kk < 16; kk++) {
            float4 a0 = *(float4*)&As[kk][ty*4];
            float4 a1 = *(float4*)&As[kk][64+ty*4];
            float4 b0 = *(float4*)&Bs[kk][tx*4];
            float4 b1 = *(float4*)&Bs[kk][64+tx*4];
            float a[8] = {a0.x,a0.y,a0.z,a0.w,a1.x,a1.y,a1.z,a1.w};
            float bv[8] = {b0.x,b0.y,b0.z,b0.w,b1.x,b1.y,b1.z,b1.w};
            #pragma unroll
            for (int i = 0; i < 8; i++)
                #pragma unroll
                for (int j = 0; j < 8; j++) acc[i][j] += a[i]*bv[j];
        }
        __syncthreads();
    }
    float bj[8];
    #pragma unroll
    for (int j = 0; j < 4; j++) { bj[j] = bias[n0+tx*4+j]; bj[4+j] = bias[n0+64+tx*4+j]; }
    #pragma unroll
    for (int ih = 0; ih < 2; ih++) {
        #pragma unroll
        for (int i = 0; i < 4; i++) {
            int row = m0 + ih*64 + ty*4 + i;
            int ai = ih*4 + i;
            float* op = Out + (long)row*Cc + n0;
            float4 o0 = {acc[ai][0]+bj[0], acc[ai][1]+bj[1], acc[ai][2]+bj[2], acc[ai][3]+bj[3]};
            float4 o1 = {acc[ai][4]+bj[4], acc[ai][5]+bj[5], acc[ai][6]+bj[6], acc[ai][7]+bj[7]};
            *(float4*)&op[tx*4]    = o0;
            *(float4*)&op[64+tx*4] = o1;
        }
    }
}

// ---------------- K5: flash attention, 64 query rows / block ----------------
// K staged with row stride 65 (scalar reads, conflict-free);
// V staged with row stride 68 (multiple of 4 -> aligned float4 reads).
#define TMq 64
#define TNK 128
#define QPAD 65
#define VPAD 68
#define PPAD 132
__global__ __launch_bounds__(256) void k_flash() {
    extern __shared__ float smf[];
    float* Qs = smf;                                // [64][65]
    float* Ks = smf + TMq*QPAD;                     // [128][68] region (K uses stride 65, V stride 68)
    float* Ps = smf + TMq*QPAD + TNK*VPAD;          // [64][132]
    int n0 = blockIdx.x*TMq, h = blockIdx.y, b = blockIdx.z;
    int tid = threadIdx.x;
    int tx = tid & 15, ty = tid >> 4;
    // load Q tile (clamped)
    for (int idx = tid; idx < TMq*16; idx += 256) {
        int r = idx >> 4, dq = (idx & 15)*4;
        int n = n0 + r; if (n > Nn-1) n = Nn-1;
        float4 v = *(const float4*)&g_q[((long)(b*Nn + n))*Cc + h*HD + dq];
        Qs[r*QPAD+dq] = v.x; Qs[r*QPAD+dq+1] = v.y; Qs[r*QPAD+dq+2] = v.z; Qs[r*QPAD+dq+3] = v.w;
    }
    float m_pr[4], l_pr[4], Oa[4][4];
    #pragma unroll
    for (int i = 0; i < 4; i++) {
        m_pr[i] = -1e30f; l_pr[i] = 0.f;
        #pragma unroll
        for (int j = 0; j < 4; j++) Oa[i][j] = 0.f;
    }
    for (int kt = 0; kt < Nn; kt += TNK) {
        __syncthreads();
        for (int idx = tid; idx < TNK*16; idx += 256) {
            int r = idx >> 4, dq = (idx & 15)*4;
            int m = kt + r; if (m > Nn-1) m = Nn-1;
            float4 v = *(const float4*)&g_k[((long)(b*Nn + m))*Cc + h*HD + dq];
            Ks[r*QPAD+dq] = v.x; Ks[r*QPAD+dq+1] = v.y; Ks[r*QPAD+dq+2] = v.z; Ks[r*QPAD+dq+3] = v.w;
        }
        __syncthreads();
        float S[4][8];
        #pragma unroll
        for (int i = 0; i < 4; i++)
            #pragma unroll
            for (int j = 0; j < 8; j++) S[i][j] = 0.f;
        #pragma unroll 4
        for (int d = 0; d < HD; d++) {
            float a[4], bv[8];
            #pragma unroll
            for (int i = 0; i < 4; i++) a[i] = Qs[(ty*4+i)*QPAD + d];
            #pragma unroll
            for (int j = 0; j < 8; j++) bv[j] = Ks[(tx + j*16)*QPAD + d];
            #pragma unroll
            for (int i = 0; i < 4; i++)
                #pragma unroll
                for (int j = 0; j < 8; j++) S[i][j] += a[i]*bv[j];
        }
        // scale + mask
        #pragma unroll
        for (int i = 0; i < 4; i++)
            #pragma unroll
            for (int j = 0; j < 8; j++) {
                int col = kt + tx + j*16;
                S[i][j] = (col < Nn) ? S[i][j]*0.125f : -1e30f;
            }
        // per-row softmax update (rows split across 16 lanes of the half-warp group)
        #pragma unroll
        for (int i = 0; i < 4; i++) {
            float rm = S[i][0];
            #pragma unroll
            for (int j = 1; j < 8; j++) rm = fmaxf(rm, S[i][j]);
            #pragma unroll
            for (int o = 1; o < 16; o <<= 1) rm = fmaxf(rm, __shfl_xor_sync(0xffffffffu, rm, o));
            float nm = fmaxf(m_pr[i], rm);
            float alpha = __expf(m_pr[i] - nm);
            float rs = 0.f;
            #pragma unroll
            for (int j = 0; j < 8; j++) { float e = __expf(S[i][j] - nm); S[i][j] = e; rs += e; }
            #pragma unroll
            for (int o = 1; o < 16; o <<= 1) rs += __shfl_xor_sync(0xffffffffu, rs, o);
            l_pr[i] = l_pr[i]*alpha + rs;
            m_pr[i] = nm;
            #pragma unroll
            for (int j = 0; j < 4; j++) Oa[i][j] *= alpha;
            #pragma unroll
            for (int j = 0; j < 8; j++) Ps[(ty*4+i)*PPAD + tx + j*16] = S[i][j];
        }
        __syncthreads();
        // load V tile (stride VPAD)
        for (int idx = tid; idx < TNK*16; idx += 256) {
            int r = idx >> 4, dq = (idx & 15)*4;
            int m = kt + r; if (m > Nn-1) m = Nn-1;
            float4 v = *(const float4*)&g_v[((long)(b*Nn + m))*Cc + h*HD + dq];
            Ks[r*VPAD+dq] = v.x; Ks[r*VPAD+dq+1] = v.y; Ks[r*VPAD+dq+2] = v.z; Ks[r*VPAD+dq+3] = v.w;
        }
        __syncthreads();
        int mmax = (Nn - kt < TNK) ? (Nn - kt) : TNK;
        for (int m2 = 0; m2 < mmax; m2++) {
            float4 v = *(float4*)&Ks[m2*VPAD + tx*4];
            #pragma unroll
            for (int i = 0; i < 4; i++) {
                float p = Ps[(ty*4+i)*PPAD + m2];
                Oa[i][0] += p*v.x; Oa[i][1] += p*v.y; Oa[i][2] += p*v.z; Oa[i][3] += p*v.w;
            }
        }
    }
    #pragma unroll
    for (int i = 0; i < 4; i++) {
        int row = n0 + ty*4 + i;
        if (row < Nn) {
            float inv = 1.f / l_pr[i];
            float4 o = {Oa[i][0]*inv, Oa[i][1]*inv, Oa[i][2]*inv, Oa[i][3]*inv};
            *(float4*)&g_att[((long)(b*Nn + row))*Cc + h*HD + tx*4] = o;
        }
    }
}

// ---------------- K6a: pooled sum of x*chs*sg over pixels ----------------
__global__ void k_pool_y2(const float* __restrict__ x) {
    int c = blockIdx.x, b = blockIdx.y;
    const float* p = x + (long)(b*Cc+c)*Nn;
    const float* sg = g_sg + b*Nn;
    float s = 0.f;
    for (int i = threadIdx.x; i < Nn; i += 256) s += p[i]*sg[i];
    __shared__ float ss[256];
    ss[threadIdx.x] = s; __syncthreads();
    for (int o = 128; o > 0; o >>= 1) { if (threadIdx.x < o) ss[threadIdx.x] += ss[threadIdx.x+o]; __syncthreads(); }
    if (threadIdx.x == 0) g_pool[b*Cc+c] = ss[0] * g_chs[b*Cc+c];
}

// ---------------- K6b: partial pooled sums of O ----------------
__global__ void k_pool_o2() {
    int b = blockIdx.x, chunk = blockIdx.y;   // (Bz,16)
    int p0 = chunk*49;
    int c = threadIdx.x;     // 256 threads, 2 channels each
    float s0 = 0.f, s1 = 0.f;
    for (int p = p0; p < p0+49; p++) {
        const float* row = g_o + (long)(b*Nn+p)*Cc;
        s0 += row[c]; s1 += row[c+256];
    }
    g_part[(long)(b*16+chunk)*Cc + c]       = s0;
    g_part[(long)(b*16+chunk)*Cc + c + 256] = s1;
}

// ---------------- K7: classifier ----------------
__global__ void k_head(const float* __restrict__ lng, const float* __restrict__ lnb,
                       const float* __restrict__ f1w, const float* __restrict__ f1b,
                       const float* __restrict__ f2w, const float* __restrict__ f2b,
                       float* __restrict__ out) {
    int b = blockIdx.x, t = threadIdx.x;   // 512 threads
    __shared__ float pv[512], ln[512], hsm[512], red[512];
    float acc = g_pool[b*Cc+t];
    #pragma unroll
    for (int j = 0; j < 16; j++) acc += g_part[(long)(b*16+j)*Cc + t];
    pv[t] = acc * (1.f/(float)Nn);
    __syncthreads();
    red[t] = pv[t]; __syncthreads();
    for (int o = 256; o > 0; o >>= 1) { if (t < o) red[t] += red[t+o]; __syncthreads(); }
    float mu = red[0] * (1.f/512.f); __syncthreads();
    float dv = pv[t] - mu;
    red[t] = dv*dv; __syncthreads();
    for (int o = 256; o > 0; o >>= 1) { if (t < o) red[t] += red[t+o]; __syncthreads(); }
    float var = red[0] * (1.f/512.f);
    float rs = rsqrtf(var + 1e-5f);
    ln[t] = dv * rs * lng[t] + lnb[t];
    __syncthreads();
    float s = f1b[t];
    for (int i = 0; i < 512; i++) s += f1w[t*512+i] * ln[i];
    hsm[t] = fmaxf(s, 0.f);
    __syncthreads();
    red[t] = f2w[t] * hsm[t]; __syncthreads();
    for (int o = 256; o > 0; o >>= 1) { if (t < o) red[t] += red[t+o]; __syncthreads(); }
    if (t == 0) out[b] = red[0] + f2b[0];
}

// ---------------- launch ----------------
extern "C" void kernel_launch(void* const* d_in, const int* in_sizes, int n_in,
                              void* d_out, int out_size) {
    const float* x       = (const float*)d_in[0];
    const float* mlp_w1  = (const float*)d_in[1];
    const float* mlp_b1  = (const float*)d_in[2];
    const float* mlp_w2  = (const float*)d_in[3];
    const float* mlp_b2  = (const float*)d_in[4];
    const float* sp_w    = (const float*)d_in[5];
    const float* sp_gam  = (const float*)d_in[6];
    const float* sp_bet  = (const float*)d_in[7];
    const float* sp_mean = (const float*)d_in[8];
    const float* sp_var  = (const float*)d_in[9];
    const float* wq      = (const float*)d_in[10];
    const float* bq      = (const float*)d_in[11];
    const float* wk      = (const float*)d_in[12];
    const float* bk      = (const float*)d_in[13];
    const float* wv      = (const float*)d_in[14];
    const float* bv      = (const float*)d_in[15];
    const float* wo      = (const float*)d_in[16];
    const float* bo      = (const float*)d_in[17];
    const float* ln_g    = (const float*)d_in[18];
    const float* ln_b    = (const float*)d_in[19];
    const float* fc1_w   = (const float*)d_in[20];
    const float* fc1_b   = (const float*)d_in[21];
    const float* fc2_w   = (const float*)d_in[22];
    const float* fc2_b   = (const float*)d_in[23];
    float* out = (float*)d_out;

    static int smem_set = 0;
    int flash_smem = (TMq*QPAD + TNK*VPAD + TMq*PPAD) * 4;   // 85,248 B
    if (!smem_set) {
        cudaFuncSetAttribute(k_flash, cudaFuncAttributeMaxDynamicSharedMemorySize, flash_smem);
        smem_set = 1;
    }

    k_pool    <<<dim3(Cc, Bz), 256>>>(x);
    k_changate<<<Bz, 256>>>(mlp_w1, mlp_b1, mlp_w2, mlp_b2);
    k_gate1   <<<dim3(Bz, 4, 8), 196>>>(x);
    k_gate2   <<<Bz, Nn>>>(sp_w, sp_gam, sp_bet, sp_mean, sp_var);

    k_gemm2<0><<<dim3(4, 98, 3), 256>>>(x, wq, wk, wv, bq, bk, bv);

    k_flash<<<dim3((Nn + TMq - 1)/TMq, NH, Bz), 256, flash_smem>>>();

    k_gemm2<3><<<dim3(4, 98, 1), 256>>>(0, wo, 0, 0, bo, 0, 0);

    k_pool_y2<<<dim3(Cc, Bz), 256>>>(x);
    k_pool_o2<<<dim3(Bz, 16), 256>>>();
    k_head  <<<Bz, 512>>>(ln_g, ln_b, fc1_w, fc1_b, fc2_w, fc2_b, out);
}